// round 8
// baseline (speedup 1.0000x reference)
#include <cuda_runtime.h>
#include <cuda_fp16.h>

#define EMB   2048
#define NSTEP 2048
#define NB    2
#define G4    (4*EMB)

#define CTAS  128
#define EPC   16          // e-values per CTA
#define NROWS 64          // 4 gates * EPC
#define NTHR  512         // 16 warps; warp w owns e-value e0+w (all 4 gates)

// K partition per row (2048 cols):
//   cols [0,512)     f32 in registers  (pair q = lane + 32*j, j in [0,8), col=2q)
//   cols [512,2048)  fp16 in smem      (uint2 pp = lane + 32*m, m in [0,12), col=512+4pp)

#define SH_W_U (NROWS*768)          // 49152 uints (fp16x2) = 192KB
#define SH_H_F (NB*EMB)             // 4096 floats = 16KB
#define SMEM_BYTES (SH_W_U*4 + SH_H_F*4)

__device__ float  g_Wcomb[(size_t)G4*EMB];      // f32 Wih+Whh
__device__ __half g_Whalf[(size_t)G4*EMB];      // fp16 copy
__device__ float  g_bcomb[G4];
__device__ float  g_hseq[(size_t)NSTEP*NB*EMB]; // [t][b][e]
__device__ unsigned g_bar;

__device__ __forceinline__ float sigmoidf_(float v) {
    return 1.0f / (1.0f + expf(-v));
}

// ---------------------------------------------------------------------------
__global__ void prep_kernel(const float* __restrict__ Wih, const float* __restrict__ Whh,
                            const float* __restrict__ bih, const float* __restrict__ bhh) {
    size_t n = (size_t)G4 * EMB;
    size_t stride = (size_t)gridDim.x * blockDim.x;
    for (size_t i = (size_t)blockIdx.x * blockDim.x + threadIdx.x; i < n; i += stride) {
        float v = Wih[i] + Whh[i];
        g_Wcomb[i] = v;
        g_Whalf[i] = __float2half(v);
    }
    int i = blockIdx.x * blockDim.x + threadIdx.x;
    if (i < G4) g_bcomb[i] = bih[i] + bhh[i];
    if (i == 0) g_bar = 0u;
}

// ---------------------------------------------------------------------------
// persistent LSTM: 128 CTAs x 512 threads (16 warps, 4/SMSP), occupancy 1.
// Warp w computes ALL 4 gates for e = e0 + w (2 batches) over full K:
// rows Rg[g] = g*EMB + e0 + w. After warp-reduce, lanes 0/1 finish the cell
// update and store h directly — no smem gate round trip, no extra syncs.
// ---------------------------------------------------------------------------
__global__ void __launch_bounds__(NTHR, 1)
lstm_kernel(const float* __restrict__ x, const float* __restrict__ Wih) {
    extern __shared__ float sh[];
    unsigned* sh_w = (unsigned*)sh;          // [64][768] fp16x2, cols [512,2048)
    float* sh_h = sh + SH_W_U;               // [2][2048]

    const int tid  = threadIdx.x;
    const int lane = tid & 31;
    const int wid  = tid >> 5;               // = e_local
    const int e0   = blockIdx.x * EPC;

    int rl[4], Rg[4];
    float bias[4];
#pragma unroll
    for (int g = 0; g < 4; g++) {
        rl[g] = g * 16 + wid;                // smem weight row
        Rg[g] = g * EMB + e0 + wid;          // global gate row
        bias[g] = g_bcomb[Rg[g]];
    }

    // fill smem fp16 weights: cols [512,2048) for the CTA's 64 rows
    {
        const int n4 = NROWS * 192;          // uint4 count (8 halves each)
        for (int i = tid; i < n4; i += NTHR) {
            int rr = i / 192, q4 = i % 192;
            int grow = (rr >> 4) * EMB + e0 + (rr & 15);
            uint4 v = *(const uint4*)&g_Whalf[(size_t)grow * EMB + 512 + q4 * 8];
            ((uint4*)sh_w)[rr * 192 + q4] = v;
        }
    }

    // register-resident f32 weight pairs: col = 2*(lane + 32*j), j in [0,8)
    float2 wreg[4][8];
#pragma unroll
    for (int g = 0; g < 4; g++)
#pragma unroll
        for (int j = 0; j < 8; j++)
            wreg[g][j] = *(const float2*)&g_Wcomb[(size_t)Rg[g] * EMB + 2 * (lane + 32 * j)];

    float c_reg = 0.0f;                      // lanes 0/1: c for (e0+wid, lane)

    for (int t = 0; t < NSTEP; t++) {
        // stage h_{t-1} (or x) into smem
        const float* src = (t == 0) ? x : &g_hseq[(size_t)(t - 1) * NB * EMB];
        {
            const float4* s4 = (const float4*)src;
            float4* d4 = (float4*)sh_h;
            d4[tid]        = __ldcg(s4 + tid);
            d4[tid + NTHR] = __ldcg(s4 + tid + NTHR);
        }
        __syncthreads();

        float acc[4][2];
#pragma unroll
        for (int g = 0; g < 4; g++) { acc[g][0] = 0.0f; acc[g][1] = 0.0f; }

        if (t == 0) {
            // gates0 = x @ W_ih^T (h0 = 0): stream W_ih f32 once
#pragma unroll 4
            for (int j = 0; j < 64; j++) {
                int k = lane + 32 * j;
                float h0 = sh_h[k], h1 = sh_h[EMB + k];
#pragma unroll
                for (int g = 0; g < 4; g++) {
                    float w = __ldg(&Wih[(size_t)Rg[g] * EMB + k]);
                    acc[g][0] += w * h0; acc[g][1] += w * h1;
                }
            }
        } else {
            // phase A: register f32 weight pairs, cols [0,512)
#pragma unroll
            for (int j = 0; j < 8; j++) {
                int c = 2 * (lane + 32 * j);
                float2 hA = *(const float2*)&sh_h[c];
                float2 hB = *(const float2*)&sh_h[EMB + c];
#pragma unroll
                for (int g = 0; g < 4; g++) {
                    float2 w = wreg[g][j];
                    acc[g][0] += w.x * hA.x; acc[g][0] += w.y * hA.y;
                    acc[g][1] += w.x * hB.x; acc[g][1] += w.y * hB.y;
                }
            }
            // phase B: smem fp16 weights, cols [512,2048), 4 cols/iter
            const uint2* sw2 = (const uint2*)sh_w;
#pragma unroll 4
            for (int m = 0; m < 12; m++) {
                int pp = lane + 32 * m;          // uint2 index in [0,384)
                int c = 512 + 4 * pp;
                float4 hA = *(const float4*)&sh_h[c];
                float4 hB = *(const float4*)&sh_h[EMB + c];
#pragma unroll
                for (int g = 0; g < 4; g++) {
                    uint2 wv = sw2[rl[g] * 384 + pp];
                    float2 w0 = __half22float2(*(__half2*)&wv.x);
                    float2 w1 = __half22float2(*(__half2*)&wv.y);
                    acc[g][0] += w0.x * hA.x; acc[g][0] += w0.y * hA.y;
                    acc[g][0] += w1.x * hA.z; acc[g][0] += w1.y * hA.w;
                    acc[g][1] += w0.x * hB.x; acc[g][1] += w0.y * hB.y;
                    acc[g][1] += w1.x * hB.z; acc[g][1] += w1.y * hB.w;
                }
            }
        }

        // full-warp butterfly reduce: every lane ends with all 8 sums
#pragma unroll
        for (int g = 0; g < 4; g++)
#pragma unroll
            for (int b = 0; b < 2; b++) {
                float v = acc[g][b];
                v += __shfl_xor_sync(0xffffffffu, v, 16);
                v += __shfl_xor_sync(0xffffffffu, v, 8);
                v += __shfl_xor_sync(0xffffffffu, v, 4);
                v += __shfl_xor_sync(0xffffffffu, v, 2);
                v += __shfl_xor_sync(0xffffffffu, v, 1);
                acc[g][b] = v;
            }

        // lanes 0/1: activation + cell update + publish h (b = lane)
        if (lane < 2) {
            float gi = acc[0][lane] + bias[0];
            float gf = acc[1][lane] + bias[1];
            float gg = acc[2][lane] + bias[2];
            float go = acc[3][lane] + bias[3];
            float cn = sigmoidf_(gf) * c_reg + sigmoidf_(gi) * tanhf(gg);
            c_reg = cn;
            float h = sigmoidf_(go) * tanhf(cn);
            g_hseq[((size_t)t * NB + lane) * EMB + e0 + wid] = h;
            if (t != NSTEP - 1) __threadfence();
        }

        // grid barrier (skip after final step)
        if (t != NSTEP - 1) {
            __syncthreads();
            if (tid == 0) {
                atomicAdd(&g_bar, 1u);
                unsigned target = (unsigned)(t + 1) * gridDim.x;
                while (*((volatile unsigned*)&g_bar) < target) { }
                __threadfence();
            }
            __syncthreads();
        }
    }
}

// ---------------------------------------------------------------------------
// output projection: out[b][t][n] = hseq[t][b][:] . W_out[n][:] + b_out[n]
// M = 4096 (m = t*2+b), N = 2048, K = 2048. 128x128x16 tile, 8x8/thread.
// ---------------------------------------------------------------------------
#define TBM 128
#define TBN 128
#define TBK 16
#define TPAD 4

__global__ void __launch_bounds__(256, 2)
out_gemm_kernel(const float* __restrict__ Wout, const float* __restrict__ bout,
                float* __restrict__ out) {
    __shared__ float As[TBK][TBM + TPAD];
    __shared__ float Bs[TBK][TBN + TPAD];

    const int tid = threadIdx.x;
    const int tx = tid & 15;     // n dir (8 cols each)
    const int ty = tid >> 4;     // m dir (8 rows each)
    const int m0 = blockIdx.y * TBM;
    const int n0 = blockIdx.x * TBN;

    float acc[8][8];
#pragma unroll
    for (int i = 0; i < 8; i++)
#pragma unroll
        for (int j = 0; j < 8; j++) acc[i][j] = 0.0f;

    for (int k0 = 0; k0 < EMB; k0 += TBK) {
#pragma unroll
        for (int u = 0; u < 2; u++) {
            int fi = tid * 2 + u;           // float4 index in [0,512)
            int row = fi >> 2;
            int kc = (fi & 3) * 4;
            float4 va = *(const float4*)&g_hseq[(size_t)(m0 + row) * EMB + k0 + kc];
            As[kc + 0][row] = va.x; As[kc + 1][row] = va.y;
            As[kc + 2][row] = va.z; As[kc + 3][row] = va.w;
            float4 vb = *(const float4*)&Wout[(size_t)(n0 + row) * EMB + k0 + kc];
            Bs[kc + 0][row] = vb.x; Bs[kc + 1][row] = vb.y;
            Bs[kc + 2][row] = vb.z; Bs[kc + 3][row] = vb.w;
        }
        __syncthreads();

#pragma unroll
        for (int k = 0; k < TBK; k++) {
            float a[8], b[8];
            *(float4*)&a[0] = *(const float4*)&As[k][ty * 8];
            *(float4*)&a[4] = *(const float4*)&As[k][ty * 8 + 4];
            *(float4*)&b[0] = *(const float4*)&Bs[k][tx * 8];
            *(float4*)&b[4] = *(const float4*)&Bs[k][tx * 8 + 4];
#pragma unroll
            for (int i = 0; i < 8; i++)
#pragma unroll
                for (int j = 0; j < 8; j++)
                    acc[i][j] += a[i] * b[j];
        }
        __syncthreads();
    }

    float bo[8];
#pragma unroll
    for (int j = 0; j < 8; j++) bo[j] = bout[n0 + tx * 8 + j];

#pragma unroll
    for (int i = 0; i < 8; i++) {
        int m = m0 + ty * 8 + i;
        int tt = m >> 1, bb = m & 1;
        float* o = &out[((size_t)bb * NSTEP + tt) * EMB + n0 + tx * 8];
#pragma unroll
        for (int j = 0; j < 8; j += 4) {
            float4 v;
            v.x = acc[i][j + 0] + bo[j + 0];
            v.y = acc[i][j + 1] + bo[j + 1];
            v.z = acc[i][j + 2] + bo[j + 2];
            v.w = acc[i][j + 3] + bo[j + 3];
            *(float4*)&o[j] = v;
        }
    }
}

// ---------------------------------------------------------------------------
extern "C" void kernel_launch(void* const* d_in, const int* in_sizes, int n_in,
                              void* d_out, int out_size) {
    const float* x    = (const float*)d_in[0];
    const float* Wih  = (const float*)d_in[1];
    const float* Whh  = (const float*)d_in[2];
    const float* bih  = (const float*)d_in[3];
    const float* bhh  = (const float*)d_in[4];
    const float* Wout = (const float*)d_in[5];
    const float* bout = (const float*)d_in[6];
    float* out = (float*)d_out;

    cudaFuncSetAttribute(lstm_kernel, cudaFuncAttributeMaxDynamicSharedMemorySize, SMEM_BYTES);

    prep_kernel<<<4096, 256>>>(Wih, Whh, bih, bhh);
    lstm_kernel<<<CTAS, NTHR, SMEM_BYTES>>>(x, Wih);
    dim3 ggrid(EMB / TBN, (NSTEP * NB) / TBM);
    out_gemm_kernel<<<ggrid, 256>>>(Wout, bout, out);
}